// round 1
// baseline (speedup 1.0000x reference)
#include <cuda_runtime.h>
#include <cstdint>

#define BSZ  4
#define NSEQ 2048
#define DIMC 1024
#define NH   16
#define DH   64
#define THREE_C (3 * DIMC)

// ---------------- scratch (no allocs allowed) ----------------
__device__ float g_Q[BSZ * NH * NSEQ * DH];   // [b,h,n,d]
__device__ float g_K[BSZ * NH * NSEQ * DH];
__device__ float g_V[BSZ * NH * NSEQ * DH];
__device__ float g_O[BSZ * NSEQ * DIMC];      // [b,n,h*64+d]
__device__ int   g_mask_is_i32;

// ---------------- mask dtype probe ----------------
// bool stored as 1 byte: random 0/1 bytes -> u32 words almost surely >1 somewhere.
// bool stored as int32: every u32 word is 0 or 1.
__global__ void detect_mask_kernel(const unsigned* __restrict__ m) {
    __shared__ int bad;
    if (threadIdx.x == 0) bad = 0;
    __syncthreads();
    for (int i = threadIdx.x; i < 4096; i += 256) {
        if (m[i] > 1u) bad = 1;  // benign race
    }
    __syncthreads();
    if (threadIdx.x == 0) g_mask_is_i32 = bad ? 0 : 1;
}

// ---------------- QKV GEMM: [8192,1024] @ [1024,3072] + bias, scatter to Q/K/V ----------------
// BM=BN=64, BK=16, 256 threads, 4x4 microtile.
__global__ __launch_bounds__(256) void qkv_gemm_kernel(
    const float* __restrict__ X, const float* __restrict__ W, const float* __restrict__ bias)
{
    __shared__ float As[16][64];   // transposed A tile: As[k][m]
    __shared__ float Bs[16][64];

    const int tid  = threadIdx.x;
    const int row0 = blockIdx.y * 64;
    const int col0 = blockIdx.x * 64;
    const int tx = tid & 15, ty = tid >> 4;

    const int aRow = tid >> 2;          // 0..63
    const int aCol = (tid & 3) * 4;     // 0,4,8,12
    const int bRow = tid >> 4;          // 0..15
    const int bCol = (tid & 15) * 4;    // 0..60

    float acc[4][4];
#pragma unroll
    for (int i = 0; i < 4; i++)
#pragma unroll
        for (int j = 0; j < 4; j++) acc[i][j] = 0.f;

    for (int k0 = 0; k0 < DIMC; k0 += 16) {
        float4 a = *(const float4*)&X[(row0 + aRow) * DIMC + k0 + aCol];
        As[aCol + 0][aRow] = a.x;
        As[aCol + 1][aRow] = a.y;
        As[aCol + 2][aRow] = a.z;
        As[aCol + 3][aRow] = a.w;
        *(float4*)&Bs[bRow][bCol] =
            *(const float4*)&W[(k0 + bRow) * THREE_C + col0 + bCol];
        __syncthreads();
#pragma unroll
        for (int kk = 0; kk < 16; kk++) {
            float4 av = *(const float4*)&As[kk][ty * 4];
            float4 bv = *(const float4*)&Bs[kk][tx * 4];
            float ar[4] = {av.x, av.y, av.z, av.w};
            float br[4] = {bv.x, bv.y, bv.z, bv.w};
#pragma unroll
            for (int i = 0; i < 4; i++)
#pragma unroll
                for (int j = 0; j < 4; j++) acc[i][j] += ar[i] * br[j];
        }
        __syncthreads();
    }

    // scatter: col c -> (three, head, d); 64-col tile stays inside one (three,head)
#pragma unroll
    for (int i = 0; i < 4; i++) {
        const int r = row0 + ty * 4 + i;
        const int b = r >> 11;           // / 2048
        const int n = r & 2047;
#pragma unroll
        for (int j = 0; j < 4; j++) {
            const int c = col0 + tx * 4 + j;
            const float val = acc[i][j] + bias[c];
            const int three = c >> 10;
            const int rem   = c & 1023;
            const int h     = rem >> 6;
            const int d     = rem & 63;
            float* dst = (three == 0) ? g_Q : (three == 1) ? g_K : g_V;
            dst[(((b * NH + h) * NSEQ) + n) * DH + d] = val;
        }
    }
}

// ---------------- Flash attention: per (b,h), 128 query rows per block ----------------
__global__ __launch_bounds__(128) void flash_attn_kernel(const void* __restrict__ mask)
{
    __shared__ float   Ksh[64][64];
    __shared__ float   Vsh[64][64];
    __shared__ uint8_t Msh[128][64];

    const int b   = blockIdx.z;
    const int h   = blockIdx.y;
    const int q0  = blockIdx.x * 128;
    const int tid = threadIdx.x;
    const int row = q0 + tid;
    const float scale = 0.125f;  // 64^-0.5

    const float* Qp    = &g_Q[((b * NH + h) * NSEQ + row) * DH];
    const float* Kbase = &g_K[(b * NH + h) * NSEQ * DH];
    const float* Vbase = &g_V[(b * NH + h) * NSEQ * DH];

    float q[64];
#pragma unroll
    for (int d = 0; d < 64; d += 4) {
        float4 t = *(const float4*)&Qp[d];
        q[d] = t.x; q[d + 1] = t.y; q[d + 2] = t.z; q[d + 3] = t.w;
    }

    float m = -1e30f, l = 0.f;
    float o[64];
#pragma unroll
    for (int d = 0; d < 64; d++) o[d] = 0.f;

    const int mi32 = g_mask_is_i32;
    const uint8_t* m8  = (const uint8_t*)mask;
    const int*     m32 = (const int*)mask;

    for (int kt = 0; kt < NSEQ; kt += 64) {
        // K/V tiles: 1024 float4 each, 8 per thread, coalesced
#pragma unroll
        for (int i = 0; i < 8; i++) {
            const int idx = tid + i * 128;
            const int r = idx >> 4;
            const int c = (idx & 15) << 2;
            *(float4*)&Ksh[r][c] = *(const float4*)&Kbase[(kt + r) * DH + c];
            *(float4*)&Vsh[r][c] = *(const float4*)&Vbase[(kt + r) * DH + c];
        }
        // mask tile: 128 q-rows x 64 keys
        const long mb = ((long)b * NSEQ + q0) * NSEQ + kt;
        if (mi32) {
#pragma unroll 8
            for (int i = 0; i < 64; i++) {
                const int e  = i * 128 + tid;
                const int qr = e >> 6, kc = e & 63;
                Msh[qr][kc] = (uint8_t)(m32[mb + (long)qr * NSEQ + kc] != 0);
            }
        } else {
#pragma unroll 8
            for (int i = 0; i < 64; i++) {
                const int e  = i * 128 + tid;
                const int qr = e >> 6, kc = e & 63;
                Msh[qr][kc] = m8[mb + (long)qr * NSEQ + kc];
            }
        }
        __syncthreads();

#pragma unroll
        for (int jc = 0; jc < 4; jc++) {
            float s[16];
#pragma unroll
            for (int jj = 0; jj < 16; jj++) s[jj] = 0.f;
            // 16 independent dot-chains, float4 LDS
#pragma unroll
            for (int d4 = 0; d4 < 16; d4++) {
                const float qa = q[d4 * 4], qb = q[d4 * 4 + 1];
                const float qc = q[d4 * 4 + 2], qd = q[d4 * 4 + 3];
#pragma unroll
                for (int jj = 0; jj < 16; jj++) {
                    float4 kv = *(const float4*)&Ksh[jc * 16 + jj][d4 * 4];
                    s[jj] += qa * kv.x + qb * kv.y + qc * kv.z + qd * kv.w;
                }
            }
            float cm = -1e30f;
#pragma unroll
            for (int jj = 0; jj < 16; jj++) {
                s[jj] *= scale;
                if (Msh[tid][jc * 16 + jj]) s[jj] = -3.4e38f;  // << m-init: exp underflows to 0
                cm = fmaxf(cm, s[jj]);
            }
            const float newm  = fmaxf(m, cm);
            const float alpha = __expf(m - newm);
            l *= alpha;
#pragma unroll
            for (int d = 0; d < 64; d++) o[d] *= alpha;
#pragma unroll
            for (int jj = 0; jj < 16; jj++) {
                const float p = __expf(s[jj] - newm);
                l += p;
#pragma unroll
                for (int d4 = 0; d4 < 16; d4++) {
                    float4 vv = *(const float4*)&Vsh[jc * 16 + jj][d4 * 4];
                    o[d4 * 4]     += p * vv.x;
                    o[d4 * 4 + 1] += p * vv.y;
                    o[d4 * 4 + 2] += p * vv.z;
                    o[d4 * 4 + 3] += p * vv.w;
                }
            }
            m = newm;
        }
        __syncthreads();
    }

    const float inv = 1.0f / l;
    float* Op = &g_O[((b * NSEQ) + row) * DIMC + h * DH];
#pragma unroll
    for (int d = 0; d < 64; d += 4) {
        float4 t;
        t.x = o[d] * inv; t.y = o[d + 1] * inv;
        t.z = o[d + 2] * inv; t.w = o[d + 3] * inv;
        *(float4*)&Op[d] = t;
    }
}

// ---------------- Projection GEMM: [8192,1024] @ [1024,1024] + bias ----------------
__global__ __launch_bounds__(256) void proj_gemm_kernel(
    const float* __restrict__ W, const float* __restrict__ bias, float* __restrict__ out)
{
    __shared__ float As[16][64];
    __shared__ float Bs[16][64];

    const int tid  = threadIdx.x;
    const int row0 = blockIdx.y * 64;
    const int col0 = blockIdx.x * 64;
    const int tx = tid & 15, ty = tid >> 4;

    const int aRow = tid >> 2;
    const int aCol = (tid & 3) * 4;
    const int bRow = tid >> 4;
    const int bCol = (tid & 15) * 4;

    float acc[4][4];
#pragma unroll
    for (int i = 0; i < 4; i++)
#pragma unroll
        for (int j = 0; j < 4; j++) acc[i][j] = 0.f;

    for (int k0 = 0; k0 < DIMC; k0 += 16) {
        float4 a = *(const float4*)&g_O[(row0 + aRow) * DIMC + k0 + aCol];
        As[aCol + 0][aRow] = a.x;
        As[aCol + 1][aRow] = a.y;
        As[aCol + 2][aRow] = a.z;
        As[aCol + 3][aRow] = a.w;
        *(float4*)&Bs[bRow][bCol] =
            *(const float4*)&W[(k0 + bRow) * DIMC + col0 + bCol];
        __syncthreads();
#pragma unroll
        for (int kk = 0; kk < 16; kk++) {
            float4 av = *(const float4*)&As[kk][ty * 4];
            float4 bv = *(const float4*)&Bs[kk][tx * 4];
            float ar[4] = {av.x, av.y, av.z, av.w};
            float br[4] = {bv.x, bv.y, bv.z, bv.w};
#pragma unroll
            for (int i = 0; i < 4; i++)
#pragma unroll
                for (int j = 0; j < 4; j++) acc[i][j] += ar[i] * br[j];
        }
        __syncthreads();
    }

#pragma unroll
    for (int i = 0; i < 4; i++) {
        const int r = row0 + ty * 4 + i;
#pragma unroll
        for (int j = 0; j < 4; j++) {
            const int c = col0 + tx * 4 + j;
            out[r * DIMC + c] = acc[i][j] + bias[c];
        }
    }
}

// ---------------- launch ----------------
extern "C" void kernel_launch(void* const* d_in, const int* in_sizes, int n_in,
                              void* d_out, int out_size)
{
    const float* x     = (const float*)d_in[0];
    const void*  mask  = d_in[1];
    const float* Wqkv  = (const float*)d_in[2];
    const float* bqkv  = (const float*)d_in[3];
    const float* Wproj = (const float*)d_in[4];
    const float* bproj = (const float*)d_in[5];
    float* out = (float*)d_out;

    detect_mask_kernel<<<1, 256>>>((const unsigned*)mask);

    dim3 g1(THREE_C / 64, (BSZ * NSEQ) / 64);   // 48 x 128
    qkv_gemm_kernel<<<g1, 256>>>(x, Wqkv, bqkv);

    dim3 g2(NSEQ / 128, NH, BSZ);               // 16 x 16 x 4
    flash_attn_kernel<<<g2, 128>>>(mask);

    dim3 g3(DIMC / 64, (BSZ * NSEQ) / 64);      // 16 x 128
    proj_gemm_kernel<<<g3, 256>>>(Wproj, bproj, out);
}

// round 2
// speedup vs baseline: 2.1014x; 2.1014x over previous
#include <cuda_runtime.h>
#include <cstdint>

#define BSZ  4
#define NSEQ 2048
#define DIMC 1024
#define NH   16
#define DH   64
#define THREE_C 3072

// ---------------- scratch (no allocs allowed) ----------------
__device__ float g_Q[BSZ * NH * NSEQ * DH];   // [b,h,n,d]  (pre-scaled by 1/8)
__device__ float g_K[BSZ * NH * NSEQ * DH];
__device__ float g_V[BSZ * NH * NSEQ * DH];
__device__ float g_O[BSZ * NSEQ * DIMC];      // [b,n,h*64+d]
__device__ int   g_mask_is_i32;

// ---------------- mask dtype probe ----------------
__global__ void detect_mask_kernel(const unsigned* __restrict__ m) {
    __shared__ int bad;
    if (threadIdx.x == 0) bad = 0;
    __syncthreads();
    for (int i = threadIdx.x; i < 4096; i += 256)
        if (m[i] > 1u) bad = 1;
    __syncthreads();
    if (threadIdx.x == 0) g_mask_is_i32 = bad ? 0 : 1;
}

// ============ QKV GEMM: [8192,1024]@[1024,3072]+bias, scatter, Q scaled ============
// 128x128 tile, BK=16, 256 threads, 8x8 micro as 2x2 of 4x4.
__global__ __launch_bounds__(256, 2) void qkv_gemm_kernel(
    const float* __restrict__ X, const float* __restrict__ W, const float* __restrict__ bias)
{
    __shared__ float As[16][128];   // [k][m]
    __shared__ float Bs[16][128];   // [k][n]

    const int tid  = threadIdx.x;
    const int tx   = tid & 15, ty = tid >> 4;
    const int row0 = blockIdx.y * 128;
    const int col0 = blockIdx.x * 128;

    const int ra = tid >> 2;            // 0..63
    const int kc = (tid & 3) << 2;      // 0,4,8,12
    const int rb = tid >> 5;            // 0..7
    const int cb = (tid & 31) << 2;     // 0..124

    float acc[2][2][4][4];
#pragma unroll
    for (int ri = 0; ri < 2; ri++)
#pragma unroll
        for (int ci = 0; ci < 2; ci++)
#pragma unroll
            for (int i = 0; i < 4; i++)
#pragma unroll
                for (int j = 0; j < 4; j++) acc[ri][ci][i][j] = 0.f;

    for (int k0 = 0; k0 < DIMC; k0 += 16) {
        float4 a0 = *(const float4*)&X[(row0 + ra) * DIMC + k0 + kc];
        float4 a1 = *(const float4*)&X[(row0 + ra + 64) * DIMC + k0 + kc];
        float4 b0 = *(const float4*)&W[(k0 + rb) * THREE_C + col0 + cb];
        float4 b1 = *(const float4*)&W[(k0 + rb + 8) * THREE_C + col0 + cb];
        As[kc + 0][ra] = a0.x; As[kc + 1][ra] = a0.y;
        As[kc + 2][ra] = a0.z; As[kc + 3][ra] = a0.w;
        As[kc + 0][ra + 64] = a1.x; As[kc + 1][ra + 64] = a1.y;
        As[kc + 2][ra + 64] = a1.z; As[kc + 3][ra + 64] = a1.w;
        *(float4*)&Bs[rb][cb]     = b0;
        *(float4*)&Bs[rb + 8][cb] = b1;
        __syncthreads();
#pragma unroll
        for (int kk = 0; kk < 16; kk++) {
            float4 af0 = *(const float4*)&As[kk][ty * 4];
            float4 af1 = *(const float4*)&As[kk][64 + ty * 4];
            float4 bf0 = *(const float4*)&Bs[kk][tx * 4];
            float4 bf1 = *(const float4*)&Bs[kk][64 + tx * 4];
            float ar[2][4] = {{af0.x, af0.y, af0.z, af0.w}, {af1.x, af1.y, af1.z, af1.w}};
            float br[2][4] = {{bf0.x, bf0.y, bf0.z, bf0.w}, {bf1.x, bf1.y, bf1.z, bf1.w}};
#pragma unroll
            for (int ri = 0; ri < 2; ri++)
#pragma unroll
                for (int ci = 0; ci < 2; ci++)
#pragma unroll
                    for (int i = 0; i < 4; i++)
#pragma unroll
                        for (int j = 0; j < 4; j++)
                            acc[ri][ci][i][j] += ar[ri][i] * br[ci][j];
        }
        __syncthreads();
    }

#pragma unroll
    for (int ri = 0; ri < 2; ri++)
#pragma unroll
        for (int i = 0; i < 4; i++) {
            const int r  = row0 + ri * 64 + ty * 4 + i;
            const int bb = r >> 11;
            const int n  = r & 2047;
#pragma unroll
            for (int ci = 0; ci < 2; ci++) {
                const int c     = col0 + ci * 64 + tx * 4;
                const int three = c >> 10;
                const int rem   = c & 1023;
                const int h     = rem >> 6;
                const int d     = rem & 63;
                float4 bv = *(const float4*)&bias[c];
                float4 v;
                v.x = acc[ri][ci][i][0] + bv.x;
                v.y = acc[ri][ci][i][1] + bv.y;
                v.z = acc[ri][ci][i][2] + bv.z;
                v.w = acc[ri][ci][i][3] + bv.w;
                if (three == 0) { v.x *= 0.125f; v.y *= 0.125f; v.z *= 0.125f; v.w *= 0.125f; }
                float* dst = (three == 0) ? g_Q : (three == 1) ? g_K : g_V;
                *(float4*)&dst[(((bb * NH + h) * NSEQ) + n) * DH + d] = v;
            }
        }
}

// ============ Flash attention: block-GEMM, 128 q-rows x 64-key tiles ============
// smem: Qtd[64][128] d-major, Ktd[64][64] d-major, Vs[64][64], Ps[128][68], Msh[128][64]
#define PS_STRIDE 68
#define ATT_SMEM ((64*128 + 64*64 + 64*64 + 128*PS_STRIDE) * 4 + 128*64)

__global__ __launch_bounds__(256, 2) void flash_attn_kernel(const void* __restrict__ mask)
{
    extern __shared__ float sm[];
    float*   Qtd = sm;                        // [64][128]
    float*   Ktd = Qtd + 64 * 128;            // [64][64]
    float*   Vs  = Ktd + 64 * 64;             // [64][64]
    float*   Ps  = Vs + 64 * 64;              // [128][68]
    uint8_t* Msh = (uint8_t*)(Ps + 128 * PS_STRIDE);  // [128][64]

    const int b   = blockIdx.z;
    const int h   = blockIdx.y;
    const int q0  = blockIdx.x * 128;
    const int tid = threadIdx.x;
    const int tx  = tid & 15, ty = tid >> 4;

    const float* __restrict__ Qg = g_Q + ((b * NH + h) * NSEQ + q0) * DH;
    const float* __restrict__ Kb = g_K + (b * NH + h) * NSEQ * DH;
    const float* __restrict__ Vb = g_V + (b * NH + h) * NSEQ * DH;

    // load Q tile (128x64) transposed -> Qtd[d][r]
#pragma unroll
    for (int it = 0; it < 8; it++) {
        const int idx = it * 256 + tid;       // float4 id, 0..2047
        const int r   = idx >> 4;
        const int dc  = (idx & 15) << 2;
        float4 v = *(const float4*)&Qg[r * DH + dc];
        Qtd[(dc + 0) * 128 + r] = v.x;
        Qtd[(dc + 1) * 128 + r] = v.y;
        Qtd[(dc + 2) * 128 + r] = v.z;
        Qtd[(dc + 3) * 128 + r] = v.w;
    }

    float mstate[8], lstate[8], O[8][4];
#pragma unroll
    for (int i = 0; i < 8; i++) {
        mstate[i] = -1e30f; lstate[i] = 0.f;
#pragma unroll
        for (int j = 0; j < 4; j++) O[i][j] = 0.f;
    }

    const int mi32 = g_mask_is_i32;
    const uint8_t* m8  = (const uint8_t*)mask;
    const int*     m32 = (const int*)mask;

    for (int kt = 0; kt < NSEQ; kt += 64) {
        // --- load K (transpose), V (copy), mask tile ---
#pragma unroll
        for (int it = 0; it < 4; it++) {
            const int idx = it * 256 + tid;   // float4 id, 0..1023
            const int r   = idx >> 4;
            const int dc  = (idx & 15) << 2;
            float4 kv = *(const float4*)&Kb[(kt + r) * DH + dc];
            Ktd[(dc + 0) * 64 + r] = kv.x;
            Ktd[(dc + 1) * 64 + r] = kv.y;
            Ktd[(dc + 2) * 64 + r] = kv.z;
            Ktd[(dc + 3) * 64 + r] = kv.w;
            *(float4*)&Vs[r * 64 + dc] = *(const float4*)&Vb[(kt + r) * DH + dc];
        }
        const long mbase = ((long)b * NSEQ + q0) * NSEQ + kt;
        if (mi32) {
#pragma unroll 8
            for (int w = 0; w < 32; w++) {
                const int idx = w * 256 + tid;           // 0..8191
                const int qr = idx >> 6, kc2 = idx & 63;
                Msh[idx] = (uint8_t)(m32[mbase + (long)qr * NSEQ + kc2] != 0);
            }
        } else {
#pragma unroll
            for (int w = 0; w < 8; w++) {
                const int idx = w * 256 + tid;           // u32 word id, 0..2047
                const int qr = idx >> 4, wc = idx & 15;
                ((unsigned*)Msh)[idx] =
                    ((const unsigned*)(m8 + mbase + (long)qr * NSEQ))[wc];
            }
        }
        __syncthreads();

        // --- S = Qs @ K^T (Q pre-scaled) ---
        float sacc[8][4];
#pragma unroll
        for (int i = 0; i < 8; i++)
#pragma unroll
            for (int j = 0; j < 4; j++) sacc[i][j] = 0.f;

#pragma unroll 8
        for (int d = 0; d < 64; d++) {
            float4 qf0 = *(const float4*)&Qtd[d * 128 + ty * 8];
            float4 qf1 = *(const float4*)&Qtd[d * 128 + ty * 8 + 4];
            float4 kf  = *(const float4*)&Ktd[d * 64 + tx * 4];
            float qa[8] = {qf0.x, qf0.y, qf0.z, qf0.w, qf1.x, qf1.y, qf1.z, qf1.w};
            float kb[4] = {kf.x, kf.y, kf.z, kf.w};
#pragma unroll
            for (int i = 0; i < 8; i++)
#pragma unroll
                for (int j = 0; j < 4; j++) sacc[i][j] += qa[i] * kb[j];
        }

        // --- online softmax + write P ---
#pragma unroll
        for (int i = 0; i < 8; i++) {
            const int r = ty * 8 + i;
            unsigned mu = *(const unsigned*)&Msh[r * 64 + tx * 4];
            float s0 = sacc[i][0], s1 = sacc[i][1], s2 = sacc[i][2], s3 = sacc[i][3];
            if (mu & 0x000000ffu) s0 = -3.4e38f;
            if (mu & 0x0000ff00u) s1 = -3.4e38f;
            if (mu & 0x00ff0000u) s2 = -3.4e38f;
            if (mu & 0xff000000u) s3 = -3.4e38f;
            float cm = fmaxf(fmaxf(s0, s1), fmaxf(s2, s3));
            cm = fmaxf(cm, __shfl_xor_sync(0xffffffffu, cm, 1));
            cm = fmaxf(cm, __shfl_xor_sync(0xffffffffu, cm, 2));
            cm = fmaxf(cm, __shfl_xor_sync(0xffffffffu, cm, 4));
            cm = fmaxf(cm, __shfl_xor_sync(0xffffffffu, cm, 8));
            const float nm    = fmaxf(mstate[i], cm);
            const float alpha = __expf(mstate[i] - nm);
            const float p0 = __expf(s0 - nm);
            const float p1 = __expf(s1 - nm);
            const float p2 = __expf(s2 - nm);
            const float p3 = __expf(s3 - nm);
            float ps = p0 + p1 + p2 + p3;
            ps += __shfl_xor_sync(0xffffffffu, ps, 1);
            ps += __shfl_xor_sync(0xffffffffu, ps, 2);
            ps += __shfl_xor_sync(0xffffffffu, ps, 4);
            ps += __shfl_xor_sync(0xffffffffu, ps, 8);
            lstate[i] = lstate[i] * alpha + ps;
            mstate[i] = nm;
            O[i][0] *= alpha; O[i][1] *= alpha; O[i][2] *= alpha; O[i][3] *= alpha;
            float4 pv = {p0, p1, p2, p3};
            *(float4*)&Ps[r * PS_STRIDE + tx * 4] = pv;
        }
        __syncthreads();

        // --- O += P @ V ---
#pragma unroll 4
        for (int k4 = 0; k4 < 16; k4++) {
            float4 vf0 = *(const float4*)&Vs[(k4 * 4 + 0) * 64 + tx * 4];
            float4 vf1 = *(const float4*)&Vs[(k4 * 4 + 1) * 64 + tx * 4];
            float4 vf2 = *(const float4*)&Vs[(k4 * 4 + 2) * 64 + tx * 4];
            float4 vf3 = *(const float4*)&Vs[(k4 * 4 + 3) * 64 + tx * 4];
#pragma unroll
            for (int i = 0; i < 8; i++) {
                float4 pf = *(const float4*)&Ps[(ty * 8 + i) * PS_STRIDE + k4 * 4];
                O[i][0] += pf.x * vf0.x + pf.y * vf1.x + pf.z * vf2.x + pf.w * vf3.x;
                O[i][1] += pf.x * vf0.y + pf.y * vf1.y + pf.z * vf2.y + pf.w * vf3.y;
                O[i][2] += pf.x * vf0.z + pf.y * vf1.z + pf.z * vf2.z + pf.w * vf3.z;
                O[i][3] += pf.x * vf0.w + pf.y * vf1.w + pf.z * vf2.w + pf.w * vf3.w;
            }
        }
        __syncthreads();
    }

#pragma unroll
    for (int i = 0; i < 8; i++) {
        const float inv = 1.0f / lstate[i];
        const int r = q0 + ty * 8 + i;
        float4 ov = {O[i][0] * inv, O[i][1] * inv, O[i][2] * inv, O[i][3] * inv};
        *(float4*)&g_O[((b * NSEQ) + r) * DIMC + h * DH + tx * 4] = ov;
    }
}

// ============ Projection GEMM: [8192,1024]@[1024,1024]+bias ============
__global__ __launch_bounds__(256, 2) void proj_gemm_kernel(
    const float* __restrict__ W, const float* __restrict__ bias, float* __restrict__ out)
{
    __shared__ float As[16][128];
    __shared__ float Bs[16][128];

    const int tid  = threadIdx.x;
    const int tx   = tid & 15, ty = tid >> 4;
    const int row0 = blockIdx.y * 128;
    const int col0 = blockIdx.x * 128;

    const int ra = tid >> 2;
    const int kc = (tid & 3) << 2;
    const int rb = tid >> 5;
    const int cb = (tid & 31) << 2;

    float acc[2][2][4][4];
#pragma unroll
    for (int ri = 0; ri < 2; ri++)
#pragma unroll
        for (int ci = 0; ci < 2; ci++)
#pragma unroll
            for (int i = 0; i < 4; i++)
#pragma unroll
                for (int j = 0; j < 4; j++) acc[ri][ci][i][j] = 0.f;

    for (int k0 = 0; k0 < DIMC; k0 += 16) {
        float4 a0 = *(const float4*)&g_O[(row0 + ra) * DIMC + k0 + kc];
        float4 a1 = *(const float4*)&g_O[(row0 + ra + 64) * DIMC + k0 + kc];
        float4 b0 = *(const float4*)&W[(k0 + rb) * DIMC + col0 + cb];
        float4 b1 = *(const float4*)&W[(k0 + rb + 8) * DIMC + col0 + cb];
        As[kc + 0][ra] = a0.x; As[kc + 1][ra] = a0.y;
        As[kc + 2][ra] = a0.z; As[kc + 3][ra] = a0.w;
        As[kc + 0][ra + 64] = a1.x; As[kc + 1][ra + 64] = a1.y;
        As[kc + 2][ra + 64] = a1.z; As[kc + 3][ra + 64] = a1.w;
        *(float4*)&Bs[rb][cb]     = b0;
        *(float4*)&Bs[rb + 8][cb] = b1;
        __syncthreads();
#pragma unroll
        for (int kk = 0; kk < 16; kk++) {
            float4 af0 = *(const float4*)&As[kk][ty * 4];
            float4 af1 = *(const float4*)&As[kk][64 + ty * 4];
            float4 bf0 = *(const float4*)&Bs[kk][tx * 4];
            float4 bf1 = *(const float4*)&Bs[kk][64 + tx * 4];
            float ar[2][4] = {{af0.x, af0.y, af0.z, af0.w}, {af1.x, af1.y, af1.z, af1.w}};
            float br[2][4] = {{bf0.x, bf0.y, bf0.z, bf0.w}, {bf1.x, bf1.y, bf1.z, bf1.w}};
#pragma unroll
            for (int ri = 0; ri < 2; ri++)
#pragma unroll
                for (int ci = 0; ci < 2; ci++)
#pragma unroll
                    for (int i = 0; i < 4; i++)
#pragma unroll
                        for (int j = 0; j < 4; j++)
                            acc[ri][ci][i][j] += ar[ri][i] * br[ci][j];
        }
        __syncthreads();
    }

#pragma unroll
    for (int ri = 0; ri < 2; ri++)
#pragma unroll
        for (int i = 0; i < 4; i++) {
            const int r = row0 + ri * 64 + ty * 4 + i;
#pragma unroll
            for (int ci = 0; ci < 2; ci++) {
                const int c = col0 + ci * 64 + tx * 4;
                float4 bv = *(const float4*)&bias[c];
                float4 v;
                v.x = acc[ri][ci][i][0] + bv.x;
                v.y = acc[ri][ci][i][1] + bv.y;
                v.z = acc[ri][ci][i][2] + bv.z;
                v.w = acc[ri][ci][i][3] + bv.w;
                *(float4*)&out[r * DIMC + c] = v;
            }
        }
}

// ---------------- launch ----------------
extern "C" void kernel_launch(void* const* d_in, const int* in_sizes, int n_in,
                              void* d_out, int out_size)
{
    const float* x     = (const float*)d_in[0];
    const void*  mask  = d_in[1];
    const float* Wqkv  = (const float*)d_in[2];
    const float* bqkv  = (const float*)d_in[3];
    const float* Wproj = (const float*)d_in[4];
    const float* bproj = (const float*)d_in[5];
    float* out = (float*)d_out;

    cudaFuncSetAttribute(flash_attn_kernel,
                         cudaFuncAttributeMaxDynamicSharedMemorySize, ATT_SMEM);

    detect_mask_kernel<<<1, 256>>>((const unsigned*)mask);

    dim3 g1(THREE_C / 128, (BSZ * NSEQ) / 128);   // 24 x 64
    qkv_gemm_kernel<<<g1, 256>>>(x, Wqkv, bqkv);

    dim3 g2(NSEQ / 128, NH, BSZ);                 // 16 x 16 x 4
    flash_attn_kernel<<<g2, 256, ATT_SMEM>>>(mask);

    dim3 g3(DIMC / 128, (BSZ * NSEQ) / 128);      // 8 x 64
    proj_gemm_kernel<<<g3, 256>>>(Wproj, bproj, out);
}

// round 8
// speedup vs baseline: 2.1934x; 1.0438x over previous
#include <cuda_runtime.h>
#include <cstdint>

#define BSZ  4
#define NSEQ 2048
#define DIMC 1024
#define NH   16
#define DH   64
#define THREE_C 3072

// ---------------- scratch (no allocs allowed) ----------------
__device__ float g_Q[BSZ * NH * NSEQ * DH];   // [b,h,n,d]  (pre-scaled by 1/8)
__device__ float g_K[BSZ * NH * NSEQ * DH];
__device__ float g_V[BSZ * NH * NSEQ * DH];
__device__ float g_O[BSZ * NSEQ * DIMC];      // [b,n,h*64+d]
__device__ int   g_mask_is_i32;

// ---------------- mask dtype probe ----------------
__global__ void detect_mask_kernel(const unsigned* __restrict__ m) {
    __shared__ int bad;
    if (threadIdx.x == 0) bad = 0;
    __syncthreads();
    for (int i = threadIdx.x; i < 4096; i += 256)
        if (m[i] > 1u) bad = 1;
    __syncthreads();
    if (threadIdx.x == 0) g_mask_is_i32 = bad ? 0 : 1;
}

// ============ QKV GEMM: [8192,1024]@[1024,3072]+bias, scatter, Q scaled ============
// 128x128 tile, BK=16, 256 threads, 8x8 micro as 2x2 of 4x4; register prefetch.
__global__ __launch_bounds__(256, 2) void qkv_gemm_kernel(
    const float* __restrict__ X, const float* __restrict__ W, const float* __restrict__ bias)
{
    __shared__ float As[16][128];   // [k][m]
    __shared__ float Bs[16][128];   // [k][n]

    const int tid  = threadIdx.x;
    const int tx   = tid & 15, ty = tid >> 4;
    const int row0 = blockIdx.y * 128;
    const int col0 = blockIdx.x * 128;

    const int ra = tid >> 2;            // 0..63
    const int kc = (tid & 3) << 2;      // 0,4,8,12
    const int rb = tid >> 5;            // 0..7
    const int cb = (tid & 31) << 2;     // 0..124

    float acc[2][2][4][4];
#pragma unroll
    for (int ri = 0; ri < 2; ri++)
#pragma unroll
        for (int ci = 0; ci < 2; ci++)
#pragma unroll
            for (int i = 0; i < 4; i++)
#pragma unroll
                for (int j = 0; j < 4; j++) acc[ri][ci][i][j] = 0.f;

    // prefetch tile 0
    float4 pa0 = *(const float4*)&X[(row0 + ra) * DIMC + kc];
    float4 pa1 = *(const float4*)&X[(row0 + ra + 64) * DIMC + kc];
    float4 pb0 = *(const float4*)&W[rb * THREE_C + col0 + cb];
    float4 pb1 = *(const float4*)&W[(rb + 8) * THREE_C + col0 + cb];

    for (int kt = 0; kt < 64; kt++) {
        As[kc + 0][ra] = pa0.x; As[kc + 1][ra] = pa0.y;
        As[kc + 2][ra] = pa0.z; As[kc + 3][ra] = pa0.w;
        As[kc + 0][ra + 64] = pa1.x; As[kc + 1][ra + 64] = pa1.y;
        As[kc + 2][ra + 64] = pa1.z; As[kc + 3][ra + 64] = pa1.w;
        *(float4*)&Bs[rb][cb]     = pb0;
        *(float4*)&Bs[rb + 8][cb] = pb1;
        __syncthreads();
        if (kt < 63) {
            const int k0 = (kt + 1) * 16;
            pa0 = *(const float4*)&X[(row0 + ra) * DIMC + k0 + kc];
            pa1 = *(const float4*)&X[(row0 + ra + 64) * DIMC + k0 + kc];
            pb0 = *(const float4*)&W[(k0 + rb) * THREE_C + col0 + cb];
            pb1 = *(const float4*)&W[(k0 + rb + 8) * THREE_C + col0 + cb];
        }
#pragma unroll
        for (int kk = 0; kk < 16; kk++) {
            float4 af0 = *(const float4*)&As[kk][ty * 4];
            float4 af1 = *(const float4*)&As[kk][64 + ty * 4];
            float4 bf0 = *(const float4*)&Bs[kk][tx * 4];
            float4 bf1 = *(const float4*)&Bs[kk][64 + tx * 4];
            float ar[2][4] = {{af0.x, af0.y, af0.z, af0.w}, {af1.x, af1.y, af1.z, af1.w}};
            float br[2][4] = {{bf0.x, bf0.y, bf0.z, bf0.w}, {bf1.x, bf1.y, bf1.z, bf1.w}};
#pragma unroll
            for (int ri = 0; ri < 2; ri++)
#pragma unroll
                for (int ci = 0; ci < 2; ci++)
#pragma unroll
                    for (int i = 0; i < 4; i++)
#pragma unroll
                        for (int j = 0; j < 4; j++)
                            acc[ri][ci][i][j] += ar[ri][i] * br[ci][j];
        }
        __syncthreads();
    }

    // scatter: col c -> (three, head, d)
#pragma unroll
    for (int ri = 0; ri < 2; ri++)
#pragma unroll
        for (int i = 0; i < 4; i++) {
            const int r  = row0 + ri * 64 + ty * 4 + i;
            const int bb = r >> 11;
            const int n  = r & 2047;
#pragma unroll
            for (int ci = 0; ci < 2; ci++) {
                const int c     = col0 + ci * 64 + tx * 4;
                const int three = c >> 10;
                const int rem   = c & 1023;
                const int h     = rem >> 6;
                const int d     = rem & 63;
                float4 bv = *(const float4*)&bias[c];
                float4 v;
                v.x = acc[ri][ci][i][0] + bv.x;
                v.y = acc[ri][ci][i][1] + bv.y;
                v.z = acc[ri][ci][i][2] + bv.z;
                v.w = acc[ri][ci][i][3] + bv.w;
                if (three == 0) { v.x *= 0.125f; v.y *= 0.125f; v.z *= 0.125f; v.w *= 0.125f; }
                float* dst = (three == 0) ? g_Q : (three == 1) ? g_K : g_V;
                *(float4*)&dst[(((bb * NH + h) * NSEQ) + n) * DH + d] = v;
            }
        }
}

// ============ Flash attention (byte-identical logic to the passing R1 kernel) ============
#define PS_STRIDE 68
#define ATT_SMEM ((64*128 + 64*64 + 64*64 + 128*PS_STRIDE) * 4 + 128*64)

__global__ __launch_bounds__(256, 2) void flash_attn_kernel(const void* __restrict__ mask)
{
    extern __shared__ float smf[];
    float*   Qtd = smf;                        // [64][128] d-major
    float*   Ktd = Qtd + 64 * 128;             // [64][64] d-major
    float*   Vs  = Ktd + 64 * 64;              // [64][64]
    float*   Ps  = Vs + 64 * 64;               // [128][68]
    uint8_t* Msh = (uint8_t*)(Ps + 128 * PS_STRIDE);

    const int b   = blockIdx.z;
    const int h   = blockIdx.y;
    const int q0  = blockIdx.x * 128;
    const int tid = threadIdx.x;
    const int tx  = tid & 15, ty = tid >> 4;

    const float* __restrict__ Qg = g_Q + ((b * NH + h) * NSEQ + q0) * DH;
    const float* __restrict__ Kb = g_K + (b * NH + h) * NSEQ * DH;
    const float* __restrict__ Vb = g_V + (b * NH + h) * NSEQ * DH;

#pragma unroll
    for (int it = 0; it < 8; it++) {
        const int idx = it * 256 + tid;
        const int r   = idx >> 4;
        const int dc  = (idx & 15) << 2;
        float4 v = *(const float4*)&Qg[r * DH + dc];
        Qtd[(dc + 0) * 128 + r] = v.x;
        Qtd[(dc + 1) * 128 + r] = v.y;
        Qtd[(dc + 2) * 128 + r] = v.z;
        Qtd[(dc + 3) * 128 + r] = v.w;
    }

    float mstate[8], lstate[8], O[8][4];
#pragma unroll
    for (int i = 0; i < 8; i++) {
        mstate[i] = -1e30f; lstate[i] = 0.f;
#pragma unroll
        for (int j = 0; j < 4; j++) O[i][j] = 0.f;
    }

    const int mi32 = g_mask_is_i32;
    const uint8_t* m8  = (const uint8_t*)mask;
    const int*     m32 = (const int*)mask;

    for (int kt = 0; kt < NSEQ; kt += 64) {
#pragma unroll
        for (int it = 0; it < 4; it++) {
            const int idx = it * 256 + tid;
            const int r   = idx >> 4;
            const int dc  = (idx & 15) << 2;
            float4 kv = *(const float4*)&Kb[(kt + r) * DH + dc];
            Ktd[(dc + 0) * 64 + r] = kv.x;
            Ktd[(dc + 1) * 64 + r] = kv.y;
            Ktd[(dc + 2) * 64 + r] = kv.z;
            Ktd[(dc + 3) * 64 + r] = kv.w;
            *(float4*)&Vs[r * 64 + dc] = *(const float4*)&Vb[(kt + r) * DH + dc];
        }
        const long mbase = ((long)b * NSEQ + q0) * NSEQ + kt;
        if (mi32) {
#pragma unroll 8
            for (int w = 0; w < 32; w++) {
                const int idx = w * 256 + tid;
                const int qr = idx >> 6, kc2 = idx & 63;
                Msh[idx] = (uint8_t)(m32[mbase + (long)qr * NSEQ + kc2] != 0);
            }
        } else {
#pragma unroll
            for (int w = 0; w < 8; w++) {
                const int idx = w * 256 + tid;
                const int qr = idx >> 4, wc = idx & 15;
                ((unsigned*)Msh)[idx] =
                    ((const unsigned*)(m8 + mbase + (long)qr * NSEQ))[wc];
            }
        }
        __syncthreads();

        float sacc[8][4];
#pragma unroll
        for (int i = 0; i < 8; i++)
#pragma unroll
            for (int j = 0; j < 4; j++) sacc[i][j] = 0.f;

#pragma unroll 8
        for (int d = 0; d < 64; d++) {
            float4 qf0 = *(const float4*)&Qtd[d * 128 + ty * 8];
            float4 qf1 = *(const float4*)&Qtd[d * 128 + ty * 8 + 4];
            float4 kf  = *(const float4*)&Ktd[d * 64 + tx * 4];
            float qa[8] = {qf0.x, qf0.y, qf0.z, qf0.w, qf1.x, qf1.y, qf1.z, qf1.w};
            float kb[4] = {kf.x, kf.y, kf.z, kf.w};
#pragma unroll
            for (int i = 0; i < 8; i++)
#pragma unroll
                for (int j = 0; j < 4; j++) sacc[i][j] += qa[i] * kb[j];
        }

#pragma unroll
        for (int i = 0; i < 8; i++) {
            const int r = ty * 8 + i;
            unsigned mu = *(const unsigned*)&Msh[r * 64 + tx * 4];
            float s0 = sacc[i][0], s1 = sacc[i][1], s2 = sacc[i][2], s3 = sacc[i][3];
            if (mu & 0x000000ffu) s0 = -3.4e38f;
            if (mu & 0x0000ff00u) s1 = -3.4e38f;
            if (mu & 0x00ff0000u) s2 = -3.4e38f;
            if (mu & 0xff000000u) s3 = -3.4e38f;
            float cm = fmaxf(fmaxf(s0, s1), fmaxf(s2, s3));
            cm = fmaxf(cm, __shfl_xor_sync(0xffffffffu, cm, 1));
            cm = fmaxf(cm, __shfl_xor_sync(0xffffffffu, cm, 2));
            cm = fmaxf(cm, __shfl_xor_sync(0xffffffffu, cm, 4));
            cm = fmaxf(cm, __shfl_xor_sync(0xffffffffu, cm, 8));
            const float nm    = fmaxf(mstate[i], cm);
            const float alpha = __expf(mstate[i] - nm);
            const float p0 = __expf(s0 - nm);
            const float p1 = __expf(s1 - nm);
            const float p2 = __expf(s2 - nm);
            const float p3 = __expf(s3 - nm);
            float ps = p0 + p1 + p2 + p3;
            ps += __shfl_xor_sync(0xffffffffu, ps, 1);
            ps += __shfl_xor_sync(0xffffffffu, ps, 2);
            ps += __shfl_xor_sync(0xffffffffu, ps, 4);
            ps += __shfl_xor_sync(0xffffffffu, ps, 8);
            lstate[i] = lstate[i] * alpha + ps;
            mstate[i] = nm;
            O[i][0] *= alpha; O[i][1] *= alpha; O[i][2] *= alpha; O[i][3] *= alpha;
            float4 pv = {p0, p1, p2, p3};
            *(float4*)&Ps[r * PS_STRIDE + tx * 4] = pv;
        }
        __syncthreads();

#pragma unroll 4
        for (int k4 = 0; k4 < 16; k4++) {
            float4 vf0 = *(const float4*)&Vs[(k4 * 4 + 0) * 64 + tx * 4];
            float4 vf1 = *(const float4*)&Vs[(k4 * 4 + 1) * 64 + tx * 4];
            float4 vf2 = *(const float4*)&Vs[(k4 * 4 + 2) * 64 + tx * 4];
            float4 vf3 = *(const float4*)&Vs[(k4 * 4 + 3) * 64 + tx * 4];
#pragma unroll
            for (int i = 0; i < 8; i++) {
                float4 pf = *(const float4*)&Ps[(ty * 8 + i) * PS_STRIDE + k4 * 4];
                O[i][0] += pf.x * vf0.x + pf.y * vf1.x + pf.z * vf2.x + pf.w * vf3.x;
                O[i][1] += pf.x * vf0.y + pf.y * vf1.y + pf.z * vf2.y + pf.w * vf3.y;
                O[i][2] += pf.x * vf0.z + pf.y * vf1.z + pf.z * vf2.z + pf.w * vf3.z;
                O[i][3] += pf.x * vf0.w + pf.y * vf1.w + pf.z * vf2.w + pf.w * vf3.w;
            }
        }
        __syncthreads();
    }

#pragma unroll
    for (int i = 0; i < 8; i++) {
        const float inv = 1.0f / lstate[i];
        const int r = q0 + ty * 8 + i;
        float4 ov = {O[i][0] * inv, O[i][1] * inv, O[i][2] * inv, O[i][3] * inv};
        *(float4*)&g_O[((b * NSEQ) + r) * DIMC + h * DH + tx * 4] = ov;
    }
}

// ============ Projection GEMM: [8192,1024]@[1024,1024]+bias; register prefetch ============
__global__ __launch_bounds__(256, 2) void proj_gemm_kernel(
    const float* __restrict__ W, const float* __restrict__ bias, float* __restrict__ out)
{
    __shared__ float As[16][128];
    __shared__ float Bs[16][128];

    const int tid  = threadIdx.x;
    const int tx   = tid & 15, ty = tid >> 4;
    const int row0 = blockIdx.y * 128;
    const int col0 = blockIdx.x * 128;

    const int ra = tid >> 2;
    const int kc = (tid & 3) << 2;
    const int rb = tid >> 5;
    const int cb = (tid & 31) << 2;

    float acc[2][2][4][4];
#pragma unroll
    for (int ri = 0; ri < 2; ri++)
#pragma unroll
        for (int ci = 0; ci < 2; ci++)
#pragma unroll
            for (int i = 0; i < 4; i++)
#pragma unroll
                for (int j = 0; j < 4; j++) acc[ri][ci][i][j] = 0.f;

    float4 pa0 = *(const float4*)&g_O[(row0 + ra) * DIMC + kc];
    float4 pa1 = *(const float4*)&g_O[(row0 + ra + 64) * DIMC + kc];
    float4 pb0 = *(const float4*)&W[rb * DIMC + col0 + cb];
    float4 pb1 = *(const float4*)&W[(rb + 8) * DIMC + col0 + cb];

    for (int kt = 0; kt < 64; kt++) {
        As[kc + 0][ra] = pa0.x; As[kc + 1][ra] = pa0.y;
        As[kc + 2][ra] = pa0.z; As[kc + 3][ra] = pa0.w;
        As[kc + 0][ra + 64] = pa1.x; As[kc + 1][ra + 64] = pa1.y;
        As[kc + 2][ra + 64] = pa1.z; As[kc + 3][ra + 64] = pa1.w;
        *(float4*)&Bs[rb][cb]     = pb0;
        *(float4*)&Bs[rb + 8][cb] = pb1;
        __syncthreads();
        if (kt < 63) {
            const int k0 = (kt + 1) * 16;
            pa0 = *(const float4*)&g_O[(row0 + ra) * DIMC + k0 + kc];
            pa1 = *(const float4*)&g_O[(row0 + ra + 64) * DIMC + k0 + kc];
            pb0 = *(const float4*)&W[(k0 + rb) * DIMC + col0 + cb];
            pb1 = *(const float4*)&W[(k0 + rb + 8) * DIMC + col0 + cb];
        }
#pragma unroll
        for (int kk = 0; kk < 16; kk++) {
            float4 af0 = *(const float4*)&As[kk][ty * 4];
            float4 af1 = *(const float4*)&As[kk][64 + ty * 4];
            float4 bf0 = *(const float4*)&Bs[kk][tx * 4];
            float4 bf1 = *(const float4*)&Bs[kk][64 + tx * 4];
            float ar[2][4] = {{af0.x, af0.y, af0.z, af0.w}, {af1.x, af1.y, af1.z, af1.w}};
            float br[2][4] = {{bf0.x, bf0.y, bf0.z, bf0.w}, {bf1.x, bf1.y, bf1.z, bf1.w}};
#pragma unroll
            for (int ri = 0; ri < 2; ri++)
#pragma unroll
                for (int ci = 0; ci < 2; ci++)
#pragma unroll
                    for (int i = 0; i < 4; i++)
#pragma unroll
                        for (int j = 0; j < 4; j++)
                            acc[ri][ci][i][j] += ar[ri][i] * br[ci][j];
        }
        __syncthreads();
    }

#pragma unroll
    for (int ri = 0; ri < 2; ri++)
#pragma unroll
        for (int i = 0; i < 4; i++) {
            const int r = row0 + ri * 64 + ty * 4 + i;
#pragma unroll
            for (int ci = 0; ci < 2; ci++) {
                const int c = col0 + ci * 64 + tx * 4;
                float4 bv = *(const float4*)&bias[c];
                float4 v;
                v.x = acc[ri][ci][i][0] + bv.x;
                v.y = acc[ri][ci][i][1] + bv.y;
                v.z = acc[ri][ci][i][2] + bv.z;
                v.w = acc[ri][ci][i][3] + bv.w;
                *(float4*)&out[r * DIMC + c] = v;
            }
        }
}

// ---------------- launch ----------------
extern "C" void kernel_launch(void* const* d_in, const int* in_sizes, int n_in,
                              void* d_out, int out_size)
{
    const float* x     = (const float*)d_in[0];
    const void*  mask  = d_in[1];
    const float* Wqkv  = (const float*)d_in[2];
    const float* bqkv  = (const float*)d_in[3];
    const float* Wproj = (const float*)d_in[4];
    const float* bproj = (const float*)d_in[5];
    float* out = (float*)d_out;

    cudaFuncSetAttribute(flash_attn_kernel,
                         cudaFuncAttributeMaxDynamicSharedMemorySize, ATT_SMEM);

    detect_mask_kernel<<<1, 256>>>((const unsigned*)mask);

    dim3 g1(THREE_C / 128, (BSZ * NSEQ) / 128);   // 24 x 64
    qkv_gemm_kernel<<<g1, 256>>>(x, Wqkv, bqkv);

    dim3 g2(NSEQ / 128, NH, BSZ);                 // 16 x 16 x 4
    flash_attn_kernel<<<g2, 256, ATT_SMEM>>>(mask);

    dim3 g3(DIMC / 128, (BSZ * NSEQ) / 128);      // 8 x 64
    proj_gemm_kernel<<<g3, 256>>>(Wproj, bproj, out);
}